// round 4
// baseline (speedup 1.0000x reference)
#include <cuda_runtime.h>
#include <cstdint>

#define T_STEPS 2048
#define BATCH   64
#define H       256
#define HHALF   128
#define TBH     (T_STEPS * BATCH * H)

typedef unsigned long long u64;

// Scratch (no cudaMalloc allowed): packed W_ih and precomputed xproj.
__device__ u64   g_Wp[(H / 2) * H];      // Wp[u][c] = pack(W_ih[c][2u], W_ih[c][2u+1]), [128][256]
__device__ float g_xproj[(size_t)TBH];   // [T*B][H]

// ---------------------------------------------------------------------------
// f32x2 helpers (Blackwell packed fp32)
// ---------------------------------------------------------------------------
__device__ __forceinline__ void fma2(u64& d, u64 a, u64 b)
{
    asm("fma.rn.f32x2 %0, %1, %2, %0;" : "+l"(d) : "l"(a), "l"(b));
}
__device__ __forceinline__ float fold2(u64 v)
{
    float lo, hi;
    asm("mov.b64 {%0, %1}, %2;" : "=f"(lo), "=f"(hi) : "l"(v));
    return lo + hi;
}
__device__ __forceinline__ uint32_t smem_u32(const void* p)
{
    uint32_t a;
    asm("{ .reg .u64 t; cvta.to.shared.u64 t, %1; cvt.u32.u64 %0, t; }"
        : "=r"(a) : "l"(p));
    return a;
}
__device__ __forceinline__ uint32_t mapa_u32(uint32_t la, uint32_t rank)
{
    uint32_t ra;
    asm("mapa.shared::cluster.u32 %0, %1, %2;" : "=r"(ra) : "r"(la), "r"(rank));
    return ra;
}
__device__ __forceinline__ void mbar_init(uint32_t addr, uint32_t cnt)
{
    asm volatile("mbarrier.init.shared.b64 [%0], %1;" :: "r"(addr), "r"(cnt) : "memory");
}
__device__ __forceinline__ void mbar_arrive_remote(uint32_t addr)
{
    asm volatile("mbarrier.arrive.release.cluster.shared::cluster.b64 _, [%0];"
                 :: "r"(addr) : "memory");
}
__device__ __forceinline__ void mbar_wait_acq_cluster(uint32_t addr, uint32_t parity)
{
    asm volatile(
        "{\n\t"
        ".reg .pred P;\n\t"
        "WL_%=:\n\t"
        "mbarrier.try_wait.parity.acquire.cluster.shared::cta.b64 P, [%0], %1, 0x989680;\n\t"
        "@P bra.uni WD_%=;\n\t"
        "bra.uni WL_%=;\n\t"
        "WD_%=:\n\t"
        "}"
        :: "r"(addr), "r"(parity) : "memory");
}

// ---------------------------------------------------------------------------
// Kernel 1: pack W_ih into pair layout. W viewed as u64[256][128] -> transpose.
// ---------------------------------------------------------------------------
__global__ void pack_wih_kernel(const float* __restrict__ W, u64* __restrict__ Wp)
{
    __shared__ u64 tile[32][33];
    const int u0 = (blockIdx.x & 3) * 32;   // 4 tiles along u (128)
    const int c0 = (blockIdx.x >> 2) * 32;  // 8 tiles along c (256)
    const u64* ullW = reinterpret_cast<const u64*>(W);
    tile[threadIdx.y][threadIdx.x] = ullW[(c0 + threadIdx.y) * (H / 2) + (u0 + threadIdx.x)];
    __syncthreads();
    Wp[(u0 + threadIdx.y) * H + (c0 + threadIdx.x)] = tile[threadIdx.x][threadIdx.y];
}

// ---------------------------------------------------------------------------
// Kernel 2: xproj[r][c] = sum_i x[r][i]*W_ih[c][i] + b_ih[c] + b_hh[c]
// 32 rows/block, 256 threads; thread tile 4 rows x 8 strided columns. f32x2.
// ---------------------------------------------------------------------------
__global__ __launch_bounds__(256, 2)
void xproj_kernel(const float* __restrict__ x, const u64* __restrict__ Wp,
                  const float* __restrict__ b_ih, const float* __restrict__ b_hh,
                  float* __restrict__ xproj)
{
    __shared__ __align__(16) u64 xs[32][H / 2];   // 32 rows x 128 k-pairs = 32KB

    const int tid = threadIdx.x;
    const size_t row0 = (size_t)blockIdx.x * 32;

    const float4* xg = reinterpret_cast<const float4*>(x + row0 * H);
    float4* xsf = reinterpret_cast<float4*>(&xs[0][0]);
    #pragma unroll
    for (int i = 0; i < 8; i++) xsf[tid + i * 256] = xg[tid + i * 256];
    __syncthreads();

    const int lane = tid & 31;   // column base; cols = lane + 32*i
    const int rg   = tid >> 5;   // warp id: rows m0..m0+3
    const int m0   = 4 * rg;

    u64 acc[4][8];
    #pragma unroll
    for (int m = 0; m < 4; m++)
        #pragma unroll
        for (int i = 0; i < 8; i++) acc[m][i] = 0ull;

    #pragma unroll 2
    for (int u = 0; u < H / 2; u++) {
        u64 w[8];
        #pragma unroll
        for (int i = 0; i < 8; i++) w[i] = __ldg(&Wp[u * H + lane + 32 * i]);
        #pragma unroll
        for (int m = 0; m < 4; m++) {
            u64 xv = xs[m0 + m][u];
            #pragma unroll
            for (int i = 0; i < 8; i++) fma2(acc[m][i], xv, w[i]);
        }
    }

    #pragma unroll
    for (int m = 0; m < 4; m++) {
        #pragma unroll
        for (int i = 0; i < 8; i++) {
            const int c = lane + 32 * i;
            float v = fold2(acc[m][i]) + b_ih[c] + b_hh[c];
            xproj[(row0 + m0 + m) * H + c] = v;
        }
    }
}

// ---------------------------------------------------------------------------
// Kernel 3: sequential scan. One 2-CTA cluster per batch row.
// W_hh slice packed (k-pairs) in registers; f32x2 mat-vec.
// Handshake: producers st.shared::cluster their h half, named-barrier among
// the 128 producer threads, then ONE release-arrive on the peer's mbarrier
// (count=1). Only the 4 peer-half warps wait. Final barrier.cluster drain.
// ---------------------------------------------------------------------------
__global__ void __cluster_dims__(2, 1, 1) __launch_bounds__(256, 1)
rnn_scan_kernel(const float* __restrict__ xproj, const float* __restrict__ hx,
                const float* __restrict__ W_hh, float* __restrict__ out,
                float* __restrict__ hlast)
{
    __shared__ __align__(16) float h_s[2][H];
    __shared__ __align__(16) float part[8][HHALF];
    __shared__ __align__(8)  u64 mbar[2];

    const int tid = threadIdx.x;
    uint32_t rank;
    asm("mov.u32 %0, %%cluster_ctarank;" : "=r"(rank));
    const int b  = blockIdx.x >> 1;
    const int j0 = (int)rank * HHALF;

    const int s  = tid >> 5;      // warp id = k-split (k0 = 32*s)
    const int c  = tid & 31;
    const int jl = 4 * c;         // 4 output columns j0+jl..+3
    const int k0 = 32 * s;

    // --- pack W_hh slice: w[r][m] = pair(W[j0+jl+r][k0+2m], W[j0+jl+r][k0+2m+1])
    u64 w[4][16];
    {
        const float* Wb = W_hh + (size_t)(j0 + jl) * H + k0;
        #pragma unroll
        for (int r = 0; r < 4; r++) {
            const ulonglong2* p = reinterpret_cast<const ulonglong2*>(Wb + r * H);
            #pragma unroll
            for (int q = 0; q < 8; q++) {
                ulonglong2 v = p[q];
                w[r][2 * q]     = v.x;
                w[r][2 * q + 1] = v.y;
            }
        }
    }

    h_s[0][tid] = hx[(size_t)b * H + tid];

    if (tid == 0) {
        mbar_init(smem_u32(&mbar[0]), 1);   // single aggregated arrive per step
        mbar_init(smem_u32(&mbar[1]), 1);
    }

    // --- remote addresses (peer h halves + peer mbarriers)
    const uint32_t pr = rank ^ 1u;
    uint32_t peerH0 = 0, peerH1 = 0, peerMb0 = 0, peerMb1 = 0;
    if (tid < HHALF) {
        peerH0  = mapa_u32(smem_u32(&h_s[0][j0 + tid]), pr);
        peerH1  = mapa_u32(smem_u32(&h_s[1][j0 + tid]), pr);
        peerMb0 = mapa_u32(smem_u32(&mbar[0]), pr);
        peerMb1 = mapa_u32(smem_u32(&mbar[1]), pr);
    }
    const uint32_t myMb0 = smem_u32(&mbar[0]);
    const uint32_t myMb1 = smem_u32(&mbar[1]);

    __syncthreads();
    // cluster-wide: mbarriers initialized + h_s[0] ready in both CTAs
    asm volatile("barrier.cluster.arrive.aligned;" ::: "memory");
    asm volatile("barrier.cluster.wait.aligned;"   ::: "memory");

    // warps whose k-range lies in the PEER's output half must wait for DSMEM
    const bool wait_warp = ((s >> 2) != (int)rank);

    // xp prefetch (one step ahead)
    const float* xpb = xproj + (size_t)b * H + j0 + tid;
    float xp = 0.0f;
    if (tid < HHALF) xp = __ldg(xpb);

    int cur = 0;
    for (int t = 0; t < T_STEPS; t++) {
        if (t > 0 && wait_warp) {
            const uint32_t mb = (t & 1) ? myMb1 : myMb0;
            const uint32_t p  = ((t - 1) >> 1) & 1;
            mbar_wait_acq_cluster(mb, p);
        }

        // --- f32x2 mat-vec partials: 4 cols x 16 k-pairs
        const ulonglong2* h2 = reinterpret_cast<const ulonglong2*>(&h_s[cur][k0]);
        u64 a0 = 0ull, a1 = 0ull, a2 = 0ull, a3 = 0ull;
        #pragma unroll
        for (int q = 0; q < 8; q++) {
            ulonglong2 hv = h2[q];
            fma2(a0, hv.x, w[0][2 * q]); fma2(a0, hv.y, w[0][2 * q + 1]);
            fma2(a1, hv.x, w[1][2 * q]); fma2(a1, hv.y, w[1][2 * q + 1]);
            fma2(a2, hv.x, w[2][2 * q]); fma2(a2, hv.y, w[2][2 * q + 1]);
            fma2(a3, hv.x, w[3][2 * q]); fma2(a3, hv.y, w[3][2 * q + 1]);
        }
        float4 pv = make_float4(fold2(a0), fold2(a1), fold2(a2), fold2(a3));
        *reinterpret_cast<float4*>(&part[s][jl]) = pv;
        __syncthreads();

        const int nxt = cur ^ 1;
        if (tid < HHALF) {
            // pairwise-tree reduction
            float v01 = part[0][tid] + part[1][tid];
            float v23 = part[2][tid] + part[3][tid];
            float v45 = part[4][tid] + part[5][tid];
            float v67 = part[6][tid] + part[7][tid];
            float v = ((v01 + v23) + (v45 + v67)) + xp;
            const float hn = tanhf(v);

            // DSMEM store FIRST (gets the release chain moving ASAP)
            const uint32_t ph = nxt ? peerH1 : peerH0;
            asm volatile("st.shared::cluster.f32 [%0], %1;" :: "r"(ph), "f"(hn) : "memory");

            // producer-group barrier (warps 0-3 only), then ONE release-arrive
            asm volatile("bar.sync 1, 128;" ::: "memory");
            if (tid == 0) {
                const uint32_t pm = ((t + 1) & 1) ? peerMb1 : peerMb0;
                mbar_arrive_remote(pm);
            }

            h_s[nxt][j0 + tid] = hn;                      // local copy
            out[(size_t)t * (BATCH * H) + (size_t)b * H + j0 + tid] = hn;
            if (hlast && t == T_STEPS - 1)
                hlast[(size_t)b * H + j0 + tid] = hn;

            if (t + 1 < T_STEPS)
                xp = __ldg(xpb + (size_t)(t + 1) * (BATCH * H));
        }
        __syncthreads();   // local h_s[nxt] visible; part[] safe to overwrite
        cur = nxt;
    }

    // Drain: peer's last-step DSMEM stores + remote arrives must land before
    // either CTA retires (exit race caused the R2 ULF).
    asm volatile("barrier.cluster.arrive.aligned;" ::: "memory");
    asm volatile("barrier.cluster.wait.aligned;"   ::: "memory");
}

// ---------------------------------------------------------------------------
extern "C" void kernel_launch(void* const* d_in, const int* in_sizes, int n_in,
                              void* d_out, int out_size)
{
    const float* x    = (const float*)d_in[0];   // [T,B,256]
    const float* hx   = (const float*)d_in[1];   // [B,256]
    const float* W_ih = (const float*)d_in[2];   // [256,256]
    const float* W_hh = (const float*)d_in[3];   // [256,256]
    const float* b_ih = (const float*)d_in[4];   // [256]
    const float* b_hh = (const float*)d_in[5];   // [256]
    float* out = (float*)d_out;

    u64*   d_Wp;
    float* d_xproj;
    cudaGetSymbolAddress((void**)&d_Wp, g_Wp);
    cudaGetSymbolAddress((void**)&d_xproj, g_xproj);

    float* hlast = (out_size >= TBH + BATCH * H) ? (out + TBH) : nullptr;

    pack_wih_kernel<<<32, dim3(32, 32)>>>(W_ih, d_Wp);
    xproj_kernel<<<(T_STEPS * BATCH) / 32, 256>>>(x, d_Wp, b_ih, b_hh, d_xproj);
    rnn_scan_kernel<<<2 * BATCH, 256>>>(d_xproj, hx, W_hh, out, hlast);
    (void)in_sizes; (void)n_in;
}

// round 5
// speedup vs baseline: 1.3966x; 1.3966x over previous
#include <cuda_runtime.h>
#include <cstdint>

#define T_STEPS 2048
#define BATCH   64
#define H       256
#define HHALF   128
#define TBH     (T_STEPS * BATCH * H)

typedef unsigned long long u64;

// Scratch (no cudaMalloc allowed): packed W_ih and precomputed xproj.
__device__ u64   g_Wp[(H / 2) * H];      // Wp[u][c] = pack(W_ih[c][2u], W_ih[c][2u+1])
__device__ float g_xproj[(size_t)TBH];   // [T*B][H]

// ---------------------------------------------------------------------------
// helpers
// ---------------------------------------------------------------------------
__device__ __forceinline__ void fma2(u64& d, u64 a, u64 b)
{
    asm("fma.rn.f32x2 %0, %1, %2, %0;" : "+l"(d) : "l"(a), "l"(b));
}
__device__ __forceinline__ float fold2(u64 v)
{
    float lo, hi;
    asm("mov.b64 {%0, %1}, %2;" : "=f"(lo), "=f"(hi) : "l"(v));
    return lo + hi;
}
__device__ __forceinline__ uint32_t smem_u32(const void* p)
{
    uint32_t a;
    asm("{ .reg .u64 t; cvta.to.shared.u64 t, %1; cvt.u32.u64 %0, t; }"
        : "=r"(a) : "l"(p));
    return a;
}
__device__ __forceinline__ uint32_t mapa_u32(uint32_t la, uint32_t rank)
{
    uint32_t ra;
    asm("mapa.shared::cluster.u32 %0, %1, %2;" : "=r"(ra) : "r"(la), "r"(rank));
    return ra;
}

// ---------------------------------------------------------------------------
// Kernel 1: pack W_ih into pair layout (u64 transpose).
// ---------------------------------------------------------------------------
__global__ void pack_wih_kernel(const float* __restrict__ W, u64* __restrict__ Wp)
{
    __shared__ u64 tile[32][33];
    const int u0 = (blockIdx.x & 3) * 32;
    const int c0 = (blockIdx.x >> 2) * 32;
    const u64* ullW = reinterpret_cast<const u64*>(W);
    tile[threadIdx.y][threadIdx.x] = ullW[(c0 + threadIdx.y) * (H / 2) + (u0 + threadIdx.x)];
    __syncthreads();
    Wp[(u0 + threadIdx.y) * H + (c0 + threadIdx.x)] = tile[threadIdx.x][threadIdx.y];
}

// ---------------------------------------------------------------------------
// Kernel 2: xproj[r][c] = sum_i x[r][i]*W_ih[c][i] + b_ih[c] + b_hh[c]  (f32x2)
// ---------------------------------------------------------------------------
__global__ __launch_bounds__(256, 2)
void xproj_kernel(const float* __restrict__ x, const u64* __restrict__ Wp,
                  const float* __restrict__ b_ih, const float* __restrict__ b_hh,
                  float* __restrict__ xproj)
{
    __shared__ __align__(16) u64 xs[32][H / 2];

    const int tid = threadIdx.x;
    const size_t row0 = (size_t)blockIdx.x * 32;

    const float4* xg = reinterpret_cast<const float4*>(x + row0 * H);
    float4* xsf = reinterpret_cast<float4*>(&xs[0][0]);
    #pragma unroll
    for (int i = 0; i < 8; i++) xsf[tid + i * 256] = xg[tid + i * 256];
    __syncthreads();

    const int lane = tid & 31;
    const int rg   = tid >> 5;
    const int m0   = 4 * rg;

    u64 acc[4][8];
    #pragma unroll
    for (int m = 0; m < 4; m++)
        #pragma unroll
        for (int i = 0; i < 8; i++) acc[m][i] = 0ull;

    #pragma unroll 2
    for (int u = 0; u < H / 2; u++) {
        u64 w[8];
        #pragma unroll
        for (int i = 0; i < 8; i++) w[i] = __ldg(&Wp[u * H + lane + 32 * i]);
        #pragma unroll
        for (int m = 0; m < 4; m++) {
            u64 xv = xs[m0 + m][u];
            #pragma unroll
            for (int i = 0; i < 8; i++) fma2(acc[m][i], xv, w[i]);
        }
    }

    #pragma unroll
    for (int m = 0; m < 4; m++) {
        #pragma unroll
        for (int i = 0; i < 8; i++) {
            const int c = lane + 32 * i;
            float v = fold2(acc[m][i]) + b_ih[c] + b_hh[c];
            xproj[(row0 + m0 + m) * H + c] = v;
        }
    }
}

// ---------------------------------------------------------------------------
// Kernel 3: scan, 2-CTA cluster per batch row, TAG-IN-DATA handshake.
// h element = (f32 value, u32 tag) packed in one 8B word. Producer writes
// peer (st.shared::cluster.b64) + local; consumers poll tags with volatile
// LDS. No mbarrier, no fences, no L1 flush. One __syncthreads per step;
// part[] double-buffered by step parity to license that.
// ---------------------------------------------------------------------------
__global__ void __cluster_dims__(2, 1, 1) __launch_bounds__(256, 1)
rnn_scan_kernel(const float* __restrict__ xproj, const float* __restrict__ hx,
                const float* __restrict__ W_hh, float* __restrict__ out,
                float* __restrict__ hlast)
{
    __shared__ __align__(16) u64 h_tag[2][H];      // (value, tag) per element
    __shared__ __align__(16) float part[2][8][HHALF];

    const int tid = threadIdx.x;
    uint32_t rank;
    asm("mov.u32 %0, %%cluster_ctarank;" : "=r"(rank));
    const int b  = blockIdx.x >> 1;
    const int j0 = (int)rank * HHALF;

    const int s    = tid >> 5;     // warp id = k-slice [32s, 32s+32)
    const int lane = tid & 31;
    const int jl   = 4 * lane;     // 4 output columns per thread
    const int k0   = 32 * s;

    // --- W_hh slice in registers as k-pairs: w[r][m] = (W[j][k0+2m], W[j][k0+2m+1])
    u64 w[4][16];
    {
        const float* Wb = W_hh + (size_t)(j0 + jl) * H + k0;
        #pragma unroll
        for (int r = 0; r < 4; r++) {
            const ulonglong2* p = reinterpret_cast<const ulonglong2*>(Wb + r * H);
            #pragma unroll
            for (int q = 0; q < 8; q++) {
                ulonglong2 v = p[q];
                w[r][2 * q]     = v.x;
                w[r][2 * q + 1] = v.y;
            }
        }
    }

    // --- init: buffer0 = (hx, tag 0); buffer1 = invalid tag
    {
        float h0 = __ldg(hx + (size_t)b * H + tid);
        u64 pv;
        asm("mov.b64 %0, {%1, %2};" : "=l"(pv) : "f"(h0), "r"(0u));
        h_tag[0][tid] = pv;
        asm("mov.b64 %0, {%1, %2};" : "=l"(pv) : "f"(0.0f), "r"(0xFFFFFFFFu));
        h_tag[1][tid] = pv;
    }
    __syncthreads();
    // both CTAs initialized before any remote store may land
    asm volatile("barrier.cluster.arrive.aligned;" ::: "memory");
    asm volatile("barrier.cluster.wait.aligned;"   ::: "memory");

    // --- addresses
    const uint32_t pollA = smem_u32(&h_tag[0][k0 + lane]);   // + buf*2048
    const uint32_t vecA  = smem_u32(&h_tag[0][k0]);          // + buf*2048 + 16*i
    uint32_t locA = 0, peerA = 0;
    if (tid < HHALF) {
        locA  = smem_u32(&h_tag[0][j0 + tid]);
        peerA = mapa_u32(locA, rank ^ 1u);
    }

    // xp prefetch (one step ahead)
    const float* xpb = xproj + (size_t)b * H + j0 + tid;
    float xp = 0.0f;
    if (tid < HHALF) xp = __ldg(xpb);

    for (int t = 0; t < T_STEPS; t++) {
        const uint32_t buf  = (uint32_t)t & 1u;
        const uint32_t boff = buf * (H * 8);

        // --- poll my k-slice: lane waits on word (k0+lane) having tag == t
        {
            const uint32_t pa = pollA + boff;
            uint32_t lo, hi;
            bool ok;
            do {
                asm volatile("ld.volatile.shared.v2.u32 {%0, %1}, [%2];"
                             : "=r"(lo), "=r"(hi) : "r"(pa) : "memory");
                ok = (hi == (uint32_t)t);
            } while (!__all_sync(0xFFFFFFFFu, ok));
        }

        // --- f32x2 mat-vec: 16 (val,tag,val,tag) vector loads -> 16 k-pairs
        u64 a0 = 0ull, a1 = 0ull, a2 = 0ull, a3 = 0ull;
        const uint32_t hb = vecA + boff;
        #pragma unroll
        for (int i = 0; i < 16; i++) {
            uint32_t v0, d0, v1, d1;
            asm volatile("ld.shared.v4.u32 {%0, %1, %2, %3}, [%4];"
                         : "=r"(v0), "=r"(d0), "=r"(v1), "=r"(d1)
                         : "r"(hb + 16 * i));
            u64 hv;
            asm("mov.b64 %0, {%1, %2};" : "=l"(hv) : "r"(v0), "r"(v1));
            fma2(a0, hv, w[0][i]);
            fma2(a1, hv, w[1][i]);
            fma2(a2, hv, w[2][i]);
            fma2(a3, hv, w[3][i]);
        }
        *reinterpret_cast<float4*>(&part[buf][s][jl]) =
            make_float4(fold2(a0), fold2(a1), fold2(a2), fold2(a3));
        __syncthreads();

        if (tid < HHALF) {
            float v01 = part[buf][0][tid] + part[buf][1][tid];
            float v23 = part[buf][2][tid] + part[buf][3][tid];
            float v45 = part[buf][4][tid] + part[buf][5][tid];
            float v67 = part[buf][6][tid] + part[buf][7][tid];
            const float hn = tanhf(((v01 + v23) + (v45 + v67)) + xp);

            if (t + 1 < T_STEPS) {
                u64 pv;
                asm("mov.b64 %0, {%1, %2};" : "=l"(pv) : "f"(hn), "r"((uint32_t)(t + 1)));
                const uint32_t noff = ((uint32_t)(t + 1) & 1u) * (H * 8);
                // remote first: starts the DSMEM transfer ASAP
                asm volatile("st.shared::cluster.b64 [%0], %1;"
                             :: "r"(peerA + noff), "l"(pv) : "memory");
                asm volatile("st.shared.b64 [%0], %1;"
                             :: "r"(locA + noff), "l"(pv) : "memory");
            }

            out[(size_t)t * (BATCH * H) + (size_t)b * H + j0 + tid] = hn;
            if (hlast && t == T_STEPS - 1)
                hlast[(size_t)b * H + j0 + tid] = hn;

            if (t + 1 < T_STEPS)
                xp = __ldg(xpb + (size_t)(t + 1) * (BATCH * H));
        }
        // no trailing __syncthreads: part[] is parity double-buffered and the
        // h-tag gate transitively orders next-step part writes after this
        // step's part reads.
    }

    // Drain before retiring (R2 lesson: no CTA may exit with peer's remote
    // stores possibly in flight toward it).
    asm volatile("barrier.cluster.arrive.aligned;" ::: "memory");
    asm volatile("barrier.cluster.wait.aligned;"   ::: "memory");
}

// ---------------------------------------------------------------------------
extern "C" void kernel_launch(void* const* d_in, const int* in_sizes, int n_in,
                              void* d_out, int out_size)
{
    const float* x    = (const float*)d_in[0];   // [T,B,256]
    const float* hx   = (const float*)d_in[1];   // [B,256]
    const float* W_ih = (const float*)d_in[2];   // [256,256]
    const float* W_hh = (const float*)d_in[3];   // [256,256]
    const float* b_ih = (const float*)d_in[4];   // [256]
    const float* b_hh = (const float*)d_in[5];   // [256]
    float* out = (float*)d_out;

    u64*   d_Wp;
    float* d_xproj;
    cudaGetSymbolAddress((void**)&d_Wp, g_Wp);
    cudaGetSymbolAddress((void**)&d_xproj, g_xproj);

    float* hlast = (out_size >= TBH + BATCH * H) ? (out + TBH) : nullptr;

    pack_wih_kernel<<<32, dim3(32, 32)>>>(W_ih, d_Wp);
    xproj_kernel<<<(T_STEPS * BATCH) / 32, 256>>>(x, d_Wp, b_ih, b_hh, d_xproj);
    rnn_scan_kernel<<<2 * BATCH, 256>>>(d_xproj, hx, W_hh, out, hlast);
    (void)in_sizes; (void)n_in;
}